// round 6
// baseline (speedup 1.0000x reference)
#include <cuda_runtime.h>

#define THREADS 256
#define BLOCKS  1184   // 148 SMs * 8 blocks, exactly one full wave at occ=8

// Self-cleaning global accumulator: last block publishes to out and resets
// state, so every graph replay sees identical initial conditions.
__device__ float        g_acc  = 0.0f;
__device__ unsigned int g_done = 0;

__global__ __launch_bounds__(THREADS)
void loss_synonymy_kernel(const float4* __restrict__ s1,
                          const float4* __restrict__ s2,
                          const float*  __restrict__ score,
                          float* __restrict__ out,
                          int B)
{
    const int lane   = threadIdx.x & 31;
    const int warp   = (blockIdx.x * THREADS + threadIdx.x) >> 5;
    const int nwarps = (gridDim.x * THREADS) >> 5;

    float acc = 0.0f;

    // Software-pipelined warp-per-row sweep: iteration i+1's loads are issued
    // BEFORE iteration i's shfl/tanh chain, so the warp always has loads in
    // flight while it sits in the ~200-cycle serial reduce chain.
    int row = warp;
    float4 a, b;
    if (row < B) {
        const long base = (long)row * 32 + lane;
        a = __ldcs(&s1[base]);
        b = __ldcs(&s2[base]);
    }

    while (row < B) {
        const int nrow = row + nwarps;

        // Prefetch next iteration (predicated off at the tail).
        float4 an, bn;
        if (nrow < B) {
            const long nbase = (long)nrow * 32 + lane;
            an = __ldcs(&s1[nbase]);
            bn = __ldcs(&s2[nbase]);
        }

        // Compute on the current row while the prefetch is in flight.
        float dx = a.x - b.x;
        float dy = a.y - b.y;
        float dz = a.z - b.z;
        float dw = a.w - b.w;
        float ss = dx*dx + dy*dy + dz*dz + dw*dw;

        #pragma unroll
        for (int off = 16; off > 0; off >>= 1)
            ss += __shfl_xor_sync(0xffffffffu, ss, off);

        float t  = tanhf(sqrtf(ss));
        float sc = __ldg(&score[row]);  // uniform across warp
        float e  = (sc >= 0.6f) ? (1.0f - t) : (1.0f + t);
        acc += fmaxf(e, 0.0f);

        a = an; b = bn;
        row = nrow;
    }

    // acc is lane-uniform after the all-reduce math; reduce warps in block.
    __shared__ float warp_sums[THREADS / 32];
    if (lane == 0) warp_sums[threadIdx.x >> 5] = acc;
    __syncthreads();

    if (threadIdx.x == 0) {
        float v = 0.0f;
        #pragma unroll
        for (int i = 0; i < THREADS / 32; i++) v += warp_sums[i];
        atomicAdd(&g_acc, v);
        __threadfence();
        unsigned int ticket = atomicAdd(&g_done, 1u);
        if (ticket == gridDim.x - 1) {
            out[0] = g_acc;   // publish
            g_acc  = 0.0f;    // reset for next replay
            g_done = 0;
        }
    }
}

extern "C" void kernel_launch(void* const* d_in, const int* in_sizes, int n_in,
                              void* d_out, int out_size)
{
    const float4* s1    = (const float4*)d_in[0];
    const float4* s2    = (const float4*)d_in[1];
    const float*  score = (const float*)d_in[2];
    float* out = (float*)d_out;

    const int B = in_sizes[2];  // synonymy_score has B elements

    loss_synonymy_kernel<<<BLOCKS, THREADS>>>(s1, s2, score, out, B);
}

// round 7
// speedup vs baseline: 1.2309x; 1.2309x over previous
#include <cuda_runtime.h>

#define THREADS 256
#define BLOCKS  1184   // 148 SMs * 8 blocks, one full wave at occ=8

// Self-cleaning global accumulator: last block publishes to out and resets
// state, so every graph replay sees identical initial conditions.
__device__ float        g_acc  = 0.0f;
__device__ unsigned int g_done = 0;

__global__ __launch_bounds__(THREADS, 8)   // force regs <= 32, occ = 8 blocks/SM
void loss_synonymy_kernel(const float4* __restrict__ s1,
                          const float4* __restrict__ s2,
                          const float*  __restrict__ score,
                          float* __restrict__ out,
                          int B)
{
    const int lane   = threadIdx.x & 31;
    const int warp   = (blockIdx.x * THREADS + threadIdx.x) >> 5;
    const int nwarps = (gridDim.x * THREADS) >> 5;

    float acc = 0.0f;

    // Two ADJACENT rows per warp iteration: 4 independent LDG.128 per lane
    // from one contiguous 2KB window (dense stream, unlike distant-row
    // unrolling), and the two reduce chains run data-parallel so the serial
    // chain is amortized over 2x the bytes. B is even -> no tail.
    const int npairs = B >> 1;
    for (int p = warp; p < npairs; p += nwarps) {
        const long base = (long)p * 64 + lane;  // row 2p starts at p*64 float4
        float4 a1 = __ldcs(&s1[base]);
        float4 b1 = __ldcs(&s2[base]);
        float4 a2 = __ldcs(&s1[base + 32]);     // row 2p+1
        float4 b2 = __ldcs(&s2[base + 32]);
        float  sc1 = __ldg(&score[2 * p]);
        float  sc2 = __ldg(&score[2 * p + 1]);

        float dx1 = a1.x - b1.x, dy1 = a1.y - b1.y, dz1 = a1.z - b1.z, dw1 = a1.w - b1.w;
        float dx2 = a2.x - b2.x, dy2 = a2.y - b2.y, dz2 = a2.z - b2.z, dw2 = a2.w - b2.w;
        float ss1 = dx1*dx1 + dy1*dy1 + dz1*dz1 + dw1*dw1;
        float ss2 = dx2*dx2 + dy2*dy2 + dz2*dz2 + dw2*dw2;

        // two independent warp all-reduces, interleaved (parallel chains)
        #pragma unroll
        for (int off = 16; off > 0; off >>= 1) {
            ss1 += __shfl_xor_sync(0xffffffffu, ss1, off);
            ss2 += __shfl_xor_sync(0xffffffffu, ss2, off);
        }

        float t1 = tanhf(sqrtf(ss1));
        float t2 = tanhf(sqrtf(ss2));
        float e1 = (sc1 >= 0.6f) ? (1.0f - t1) : (1.0f + t1);
        float e2 = (sc2 >= 0.6f) ? (1.0f - t2) : (1.0f + t2);
        acc += fmaxf(e1, 0.0f) + fmaxf(e2, 0.0f);
    }

    // acc is lane-uniform after the all-reduce math; reduce warps in block.
    __shared__ float warp_sums[THREADS / 32];
    if (lane == 0) warp_sums[threadIdx.x >> 5] = acc;
    __syncthreads();

    if (threadIdx.x == 0) {
        float v = 0.0f;
        #pragma unroll
        for (int i = 0; i < THREADS / 32; i++) v += warp_sums[i];
        atomicAdd(&g_acc, v);
        __threadfence();
        unsigned int ticket = atomicAdd(&g_done, 1u);
        if (ticket == gridDim.x - 1) {
            out[0] = g_acc;   // publish
            g_acc  = 0.0f;    // reset for next replay
            g_done = 0;
        }
    }
}

extern "C" void kernel_launch(void* const* d_in, const int* in_sizes, int n_in,
                              void* d_out, int out_size)
{
    const float4* s1    = (const float4*)d_in[0];
    const float4* s2    = (const float4*)d_in[1];
    const float*  score = (const float*)d_in[2];
    float* out = (float*)d_out;

    const int B = in_sizes[2];  // synonymy_score has B elements

    loss_synonymy_kernel<<<BLOCKS, THREADS>>>(s1, s2, score, out, B);
}